// round 10
// baseline (speedup 1.0000x reference)
#include <cuda_runtime.h>

#define HDIM 1024
#define BNUM 65536
#define NCOL 6                 // 2 joint + 4 group heads (g*2+c)
#define FOLD_BLOCKS 256
#define ROWS_PER_FOLD (HDIM / FOLD_BLOCKS)   // 4

// Scratch (device globals — no allocation allowed)
__device__ float g_part[FOLD_BLOCKS][NCOL][HDIM];  // 6 MB partials
__device__ float g_M[NCOL * HDIM];                 // folded matrix, [j][h]
__device__ float g_bias[NCOL];

__device__ __forceinline__ const float* col_wvec(int j, const float* W_joint, const float* W_groups) {
    return (j < 2) ? (W_joint + j * HDIM) : (W_groups + (j - 2) * HDIM);
}

// ---------------------------------------------------------------------------
// Fold stage 1: block (k, half) owns W_phi rows [4k,4k+4) x cols [512*half, +512).
// partial_k[j][h] = sum_{r in stripe} V[r][j] * W_phi[r][h]
// 512 blocks x 128 threads (2x the parallelism of R6 — it was latency-bound).
// ---------------------------------------------------------------------------
__global__ void __launch_bounds__(128) fold_part_kernel(const float* __restrict__ W_phi,
                                                        const float* __restrict__ W_groups,
                                                        const float* __restrict__ W_joint) {
    __shared__ float sV[ROWS_PER_FOLD][NCOL];
    int t = threadIdx.x, k = blockIdx.x;
    int r0 = k * ROWS_PER_FOLD;
    if (t < ROWS_PER_FOLD * NCOL) {
        int r = t / NCOL, j = t % NCOL;
        sV[r][j] = col_wvec(j, W_joint, W_groups)[r0 + r];
    }
    __syncthreads();

    int c0 = blockIdx.y * 512 + t * 4;
    float acc[NCOL][4];
    #pragma unroll
    for (int j = 0; j < NCOL; j++)
        acc[j][0] = acc[j][1] = acc[j][2] = acc[j][3] = 0.f;

    #pragma unroll
    for (int r = 0; r < ROWS_PER_FOLD; r++) {
        float4 w = *(const float4*)(W_phi + (size_t)(r0 + r) * HDIM + c0);
        #pragma unroll
        for (int j = 0; j < NCOL; j++) {
            float v = sV[r][j];
            acc[j][0] += v * w.x; acc[j][1] += v * w.y;
            acc[j][2] += v * w.z; acc[j][3] += v * w.w;
        }
    }
    #pragma unroll
    for (int j = 0; j < NCOL; j++)
        *(float4*)&g_part[k][j][c0] = make_float4(acc[j][0], acc[j][1], acc[j][2], acc[j][3]);
}

// ---------------------------------------------------------------------------
// Fold stage 2: blocks 0..95 reduce 256 partials (split-k by 4, shared
// combine, deterministic). Block 96 computes g_bias.
// ---------------------------------------------------------------------------
__global__ void __launch_bounds__(256) fold_reduce_kernel(const float* __restrict__ b_phi,
                                                          const float* __restrict__ W_groups,
                                                          const float* __restrict__ b_groups,
                                                          const float* __restrict__ W_joint,
                                                          const float* __restrict__ b_joint) {
    if (blockIdx.x == 96) {
        int w = threadIdx.x >> 5, lane = threadIdx.x & 31;
        if (w >= NCOL) return;
        const float* wv = col_wvec(w, W_joint, W_groups);
        float s = 0.f;
        #pragma unroll 4
        for (int h = lane; h < HDIM; h += 32) s += b_phi[h] * wv[h];
        #pragma unroll
        for (int o = 16; o > 0; o >>= 1) s += __shfl_down_sync(0xffffffffu, s, o);
        if (lane == 0) g_bias[w] = s + ((w < 2) ? b_joint[w] : b_groups[w - 2]);
        return;
    }
    __shared__ float red[256];
    int t = threadIdx.x;
    int idx = blockIdx.x * 64 + (t & 63);     // 96*64 = 6144 outputs
    int qk  = t >> 6;                         // split-k quarter: 64 partials each
    const float* p = (const float*)g_part;
    float s = 0.f;
    #pragma unroll 8
    for (int k = 0; k < FOLD_BLOCKS / 4; k++)
        s += p[(size_t)(qk * (FOLD_BLOCKS / 4) + k) * NCOL * HDIM + idx];
    red[t] = s;
    __syncthreads();
    if (t < 64)
        g_M[blockIdx.x * 64 + t] = (red[t] + red[t + 64]) + (red[t + 128] + red[t + 192]);
}

// ---------------------------------------------------------------------------
// Main: warp-cooperative, barrier-free hot loop. Warp processes 16 rows.
// Lane (sub=lane>>3, q=lane&7) owns rows R0+sub+4*rr (rr=0..3) and h-slice
// i*32+q*4. Each LDG.128 warp-instr covers exactly 4 x 128B lines; each
// LDS.128 reads ONE 128B line broadcast 4-ways. M smem traffic amortized
// over 4 rows -> DRAM-bound.
// ---------------------------------------------------------------------------
__global__ void __launch_bounds__(256) main_kernel(const float* __restrict__ X,
                                                   const int* __restrict__ D,
                                                   const int* __restrict__ Dagn,
                                                   float* __restrict__ out) {
    __shared__ float sM[NCOL * HDIM];   // 24 KB, [j][h]
    __shared__ float sb[NCOL];
    int t = threadIdx.x;
    {
        const float4* src = (const float4*)g_M;
        float4* dst = (float4*)sM;
        #pragma unroll
        for (int i = 0; i < (NCOL * HDIM / 4) / 256; i++)
            dst[t + i * 256] = src[t + i * 256];
        if (t < NCOL) sb[t] = g_bias[t];
    }
    __syncthreads();

    int lane = t & 31, w = t >> 5;
    int sub = lane >> 3;          // row within 4-row group
    int q   = lane & 7;           // 128B-column slot
    int q4  = q * 4;

    int R0 = blockIdx.x * 128 + w * 16;           // warp's 16 rows
    const float* xb = X + (size_t)(R0 + sub) * HDIM + q4;

    float acc[NCOL][4];
    #pragma unroll
    for (int j = 0; j < NCOL; j++)
        acc[j][0] = acc[j][1] = acc[j][2] = acc[j][3] = 0.f;

    #pragma unroll 2
    for (int i = 0; i < 32; i++) {
        float4 x0 = *(const float4*)(xb + (size_t)0  * HDIM + i * 32);
        float4 x1 = *(const float4*)(xb + (size_t)4  * HDIM + i * 32);
        float4 x2 = *(const float4*)(xb + (size_t)8  * HDIM + i * 32);
        float4 x3 = *(const float4*)(xb + (size_t)12 * HDIM + i * 32);
        const float* mb = sM + i * 32 + q4;
        #pragma unroll
        for (int j = 0; j < NCOL; j++) {
            float4 m = *(const float4*)(mb + j * HDIM);   // one 128B line, bcast
            acc[j][0] += x0.x*m.x + x0.y*m.y + x0.z*m.z + x0.w*m.w;
            acc[j][1] += x1.x*m.x + x1.y*m.y + x1.z*m.z + x1.w*m.w;
            acc[j][2] += x2.x*m.x + x2.y*m.y + x2.z*m.z + x2.w*m.w;
            acc[j][3] += x3.x*m.x + x3.y*m.y + x3.z*m.z + x3.w*m.w;
        }
    }

    // butterfly over q (lane bits 0..2): sum the 8 h-slices
    #pragma unroll
    for (int o = 1; o < 8; o <<= 1) {
        #pragma unroll
        for (int j = 0; j < NCOL; j++) {
            acc[j][0] += __shfl_xor_sync(0xffffffffu, acc[j][0], o);
            acc[j][1] += __shfl_xor_sync(0xffffffffu, acc[j][1], o);
            acc[j][2] += __shfl_xor_sync(0xffffffffu, acc[j][2], o);
            acc[j][3] += __shfl_xor_sync(0xffffffffu, acc[j][3], o);
        }
    }

    if (q == 0) {
        #pragma unroll
        for (int rr = 0; rr < 4; rr++) {
            int row = R0 + sub + 4 * rr;
            int d  = D[row];
            int da = Dagn[row];
            float j0  = acc[0][rr] + sb[0], j1  = acc[1][rr] + sb[1];
            float g00 = acc[2][rr] + sb[2], g01 = acc[3][rr] + sb[3];
            float g10 = acc[4][rr] + sb[4], g11 = acc[5][rr] + sb[5];
            *(float2*)(out + (size_t)row * 2) = make_float2(j0, j1);
            float2 gs = (d == 0)  ? make_float2(g00, g01) : make_float2(g10, g11);
            *(float2*)(out + (size_t)(BNUM + row) * 2) = gs;
            float2 ga = (da == 0) ? make_float2(g00, g01) : make_float2(g10, g11);
            *(float2*)(out + (size_t)(2 * BNUM + row) * 2) = ga;
        }
    }
}

// ---------------------------------------------------------------------------
extern "C" void kernel_launch(void* const* d_in, const int* in_sizes, int n_in,
                              void* d_out, int out_size) {
    const float* X        = (const float*)d_in[0];
    const float* W_phi    = (const float*)d_in[1];
    const float* b_phi    = (const float*)d_in[2];
    const float* W_groups = (const float*)d_in[3];
    const float* b_groups = (const float*)d_in[4];
    const float* W_joint  = (const float*)d_in[5];
    const float* b_joint  = (const float*)d_in[6];
    const int*   D        = (const int*)d_in[7];
    const int*   Dagn     = (const int*)d_in[8];
    float* out = (float*)d_out;

    fold_part_kernel<<<dim3(FOLD_BLOCKS, 2), 128>>>(W_phi, W_groups, W_joint);
    fold_reduce_kernel<<<97, 256>>>(b_phi, W_groups, b_groups, W_joint, b_joint);
    main_kernel<<<BNUM / 128, 256>>>(X, D, Dagn, out);
}

// round 11
// speedup vs baseline: 1.0953x; 1.0953x over previous
#include <cuda_runtime.h>

#define HDIM 1024
#define BNUM 65536
#define NCOL 6                 // 2 joint + 4 group heads (g*2+c)
#define FOLD_BLOCKS 256
#define ROWS_PER_FOLD (HDIM / FOLD_BLOCKS)   // 4

typedef unsigned long long u64;

// Scratch (device globals — no allocation allowed)
__device__ float g_part[FOLD_BLOCKS][NCOL][HDIM];  // 6 MB partials
__device__ float g_M[NCOL * HDIM];                 // folded matrix, [j][h]
__device__ float g_bias[NCOL];

__device__ __forceinline__ const float* col_wvec(int j, const float* W_joint, const float* W_groups) {
    return (j < 2) ? (W_joint + j * HDIM) : (W_groups + (j - 2) * HDIM);
}

// packed f32x2 FMA: acc(.lo,.hi) += a(.lo,.hi) * b(.lo,.hi)
__device__ __forceinline__ void ffma2(u64& acc, u64 a, u64 b) {
    asm("fma.rn.f32x2 %0, %1, %2, %0;" : "+l"(acc) : "l"(a), "l"(b));
}
__device__ __forceinline__ float unpack_sum(u64 a) {
    return __uint_as_float((unsigned)(a & 0xffffffffu)) + __uint_as_float((unsigned)(a >> 32));
}

// ---------------------------------------------------------------------------
// Fold stage 1: block k owns W_phi rows [4k, 4k+4) (coalesced full rows).
// partial_k[j][h] = sum_{r in stripe} V[r][j] * W_phi[r][h]
// ---------------------------------------------------------------------------
__global__ void __launch_bounds__(256) fold_part_kernel(const float* __restrict__ W_phi,
                                                        const float* __restrict__ W_groups,
                                                        const float* __restrict__ W_joint) {
    __shared__ float sV[ROWS_PER_FOLD][NCOL];
    int t = threadIdx.x, k = blockIdx.x;
    int r0 = k * ROWS_PER_FOLD;
    if (t < ROWS_PER_FOLD * NCOL) {
        int r = t / NCOL, j = t % NCOL;
        sV[r][j] = col_wvec(j, W_joint, W_groups)[r0 + r];
    }
    __syncthreads();

    int c0 = t * 4;
    float acc[NCOL][4];
    #pragma unroll
    for (int j = 0; j < NCOL; j++)
        acc[j][0] = acc[j][1] = acc[j][2] = acc[j][3] = 0.f;

    #pragma unroll
    for (int r = 0; r < ROWS_PER_FOLD; r++) {
        float4 w = *(const float4*)(W_phi + (size_t)(r0 + r) * HDIM + c0);
        #pragma unroll
        for (int j = 0; j < NCOL; j++) {
            float v = sV[r][j];
            acc[j][0] += v * w.x; acc[j][1] += v * w.y;
            acc[j][2] += v * w.z; acc[j][3] += v * w.w;
        }
    }
    #pragma unroll
    for (int j = 0; j < NCOL; j++)
        *(float4*)&g_part[k][j][c0] = make_float4(acc[j][0], acc[j][1], acc[j][2], acc[j][3]);
}

// ---------------------------------------------------------------------------
// Fold stage 2: blocks 0..95 reduce 256 partials (split-k by 4, shared
// combine, deterministic). Block 96 computes g_bias.
// ---------------------------------------------------------------------------
__global__ void __launch_bounds__(256) fold_reduce_kernel(const float* __restrict__ b_phi,
                                                          const float* __restrict__ W_groups,
                                                          const float* __restrict__ b_groups,
                                                          const float* __restrict__ W_joint,
                                                          const float* __restrict__ b_joint) {
    if (blockIdx.x == 96) {
        int w = threadIdx.x >> 5, lane = threadIdx.x & 31;
        if (w >= NCOL) return;
        const float* wv = col_wvec(w, W_joint, W_groups);
        float s = 0.f;
        #pragma unroll 4
        for (int h = lane; h < HDIM; h += 32) s += b_phi[h] * wv[h];
        #pragma unroll
        for (int o = 16; o > 0; o >>= 1) s += __shfl_down_sync(0xffffffffu, s, o);
        if (lane == 0) g_bias[w] = s + ((w < 2) ? b_joint[w] : b_groups[w - 2]);
        return;
    }
    __shared__ float red[256];
    int t = threadIdx.x;
    int idx = blockIdx.x * 64 + (t & 63);     // 96*64 = 6144 outputs
    int qk  = t >> 6;                         // split-k quarter: 64 partials each
    const float* p = (const float*)g_part;
    float s = 0.f;
    #pragma unroll 8
    for (int k = 0; k < FOLD_BLOCKS / 4; k++)
        s += p[(size_t)(qk * (FOLD_BLOCKS / 4) + k) * NCOL * HDIM + idx];
    red[t] = s;
    __syncthreads();
    if (t < 64)
        g_M[blockIdx.x * 64 + t] = (red[t] + red[t + 64]) + (red[t + 128] + red[t + 192]);
}

// ---------------------------------------------------------------------------
// Main: warp-cooperative, barrier-free hot loop; packed f32x2 FMAs.
// Warp handles 16 rows. Lane (sub=lane>>3, q=lane&7): rows R0+sub+4*rr,
// h-slice i*32+q*4. X and M loaded as ulonglong2 (two f32x2 operands per
// 128-bit load — zero packing cost). Accumulators are (even-h, odd-h)
// packed partials, unpacked once at the end. Software-pipelined prefetch.
// ---------------------------------------------------------------------------
__global__ void __launch_bounds__(256) main_kernel(const float* __restrict__ X,
                                                   const int* __restrict__ D,
                                                   const int* __restrict__ Dagn,
                                                   float* __restrict__ out) {
    __shared__ __align__(16) float sM[NCOL * HDIM];   // 24 KB, [j][h]
    __shared__ float sb[NCOL];
    int t = threadIdx.x;
    {
        const float4* src = (const float4*)g_M;
        float4* dst = (float4*)sM;
        #pragma unroll
        for (int i = 0; i < (NCOL * HDIM / 4) / 256; i++)
            dst[t + i * 256] = src[t + i * 256];
        if (t < NCOL) sb[t] = g_bias[t];
    }
    __syncthreads();

    int lane = t & 31, w = t >> 5;
    int sub = lane >> 3;          // row within 4-row group
    int q   = lane & 7;           // 128B-column slot
    int q4  = q * 4;

    int R0 = blockIdx.x * 128 + w * 16;           // warp's 16 rows
    const float* xb = X + (size_t)(R0 + sub) * HDIM + q4;

    u64 acc[NCOL][4][2];
    #pragma unroll
    for (int j = 0; j < NCOL; j++)
        #pragma unroll
        for (int rr = 0; rr < 4; rr++)
            acc[j][rr][0] = acc[j][rr][1] = 0ull;

    // prefetch iteration 0 (streaming loads — X is read exactly once)
    ulonglong2 xv[4];
    #pragma unroll
    for (int rr = 0; rr < 4; rr++)
        xv[rr] = __ldcs((const ulonglong2*)(xb + (size_t)(4 * rr) * HDIM));

    #pragma unroll 2
    for (int i = 0; i < 32; i++) {
        ulonglong2 xn[4];
        if (i + 1 < 32) {
            #pragma unroll
            for (int rr = 0; rr < 4; rr++)
                xn[rr] = __ldcs((const ulonglong2*)(xb + (size_t)(4 * rr) * HDIM + (i + 1) * 32));
        }
        const float* mb = sM + i * 32 + q4;
        #pragma unroll
        for (int j = 0; j < NCOL; j++) {
            ulonglong2 m = *(const ulonglong2*)(mb + j * HDIM);   // one 128B line, bcast
            #pragma unroll
            for (int rr = 0; rr < 4; rr++) {
                ffma2(acc[j][rr][0], xv[rr].x, m.x);
                ffma2(acc[j][rr][1], xv[rr].y, m.y);
            }
        }
        #pragma unroll
        for (int rr = 0; rr < 4; rr++) xv[rr] = xn[rr];
    }

    // collapse packed halves, then butterfly over q (lane bits 0..2)
    float a[NCOL][4];
    #pragma unroll
    for (int j = 0; j < NCOL; j++)
        #pragma unroll
        for (int rr = 0; rr < 4; rr++) {
            float s = unpack_sum(acc[j][rr][0]) + unpack_sum(acc[j][rr][1]);
            #pragma unroll
            for (int o = 1; o < 8; o <<= 1) s += __shfl_xor_sync(0xffffffffu, s, o);
            a[j][rr] = s;
        }

    if (q == 0) {
        #pragma unroll
        for (int rr = 0; rr < 4; rr++) {
            int row = R0 + sub + 4 * rr;
            int d  = D[row];
            int da = Dagn[row];
            float j0  = a[0][rr] + sb[0], j1  = a[1][rr] + sb[1];
            float g00 = a[2][rr] + sb[2], g01 = a[3][rr] + sb[3];
            float g10 = a[4][rr] + sb[4], g11 = a[5][rr] + sb[5];
            *(float2*)(out + (size_t)row * 2) = make_float2(j0, j1);
            float2 gs = (d == 0)  ? make_float2(g00, g01) : make_float2(g10, g11);
            *(float2*)(out + (size_t)(BNUM + row) * 2) = gs;
            float2 ga = (da == 0) ? make_float2(g00, g01) : make_float2(g10, g11);
            *(float2*)(out + (size_t)(2 * BNUM + row) * 2) = ga;
        }
    }
}

// ---------------------------------------------------------------------------
extern "C" void kernel_launch(void* const* d_in, const int* in_sizes, int n_in,
                              void* d_out, int out_size) {
    const float* X        = (const float*)d_in[0];
    const float* W_phi    = (const float*)d_in[1];
    const float* b_phi    = (const float*)d_in[2];
    const float* W_groups = (const float*)d_in[3];
    const float* b_groups = (const float*)d_in[4];
    const float* W_joint  = (const float*)d_in[5];
    const float* b_joint  = (const float*)d_in[6];
    const int*   D        = (const int*)d_in[7];
    const int*   Dagn     = (const int*)d_in[8];
    float* out = (float*)d_out;

    fold_part_kernel<<<FOLD_BLOCKS, 256>>>(W_phi, W_groups, W_joint);
    fold_reduce_kernel<<<97, 256>>>(b_phi, W_groups, b_groups, W_joint, b_joint);
    main_kernel<<<BNUM / 128, 256>>>(X, D, Dagn, out);
}

// round 12
// speedup vs baseline: 1.4028x; 1.2808x over previous
#include <cuda_runtime.h>

#define HDIM 1024
#define BNUM 65536
#define NCOL 6                 // 2 joint + 4 group heads (g*2+c)
#define FOLD_BLOCKS 256
#define ROWS_PER_FOLD (HDIM / FOLD_BLOCKS)   // 4

typedef unsigned long long u64;

// Scratch (device globals — no allocation allowed)
__device__ float g_part[FOLD_BLOCKS][NCOL][HDIM];  // 6 MB partials
__device__ float g_M[NCOL * HDIM];                 // folded matrix, [j][h]
__device__ float g_bias[NCOL];

__device__ __forceinline__ const float* col_wvec(int j, const float* W_joint, const float* W_groups) {
    return (j < 2) ? (W_joint + j * HDIM) : (W_groups + (j - 2) * HDIM);
}

// packed f32x2 FMA: acc(.lo,.hi) += a(.lo,.hi) * b(.lo,.hi)
__device__ __forceinline__ void ffma2(u64& acc, u64 a, u64 b) {
    asm("fma.rn.f32x2 %0, %1, %2, %0;" : "+l"(acc) : "l"(a), "l"(b));
}
__device__ __forceinline__ float unpack_sum(u64 a) {
    return __uint_as_float((unsigned)(a & 0xffffffffu)) + __uint_as_float((unsigned)(a >> 32));
}

// ---------------------------------------------------------------------------
// Fold stage 1: block k owns W_phi rows [4k, 4k+4) (coalesced full rows).
// ---------------------------------------------------------------------------
__global__ void __launch_bounds__(256) fold_part_kernel(const float* __restrict__ W_phi,
                                                        const float* __restrict__ W_groups,
                                                        const float* __restrict__ W_joint) {
    __shared__ float sV[ROWS_PER_FOLD][NCOL];
    int t = threadIdx.x, k = blockIdx.x;
    int r0 = k * ROWS_PER_FOLD;
    if (t < ROWS_PER_FOLD * NCOL) {
        int r = t / NCOL, j = t % NCOL;
        sV[r][j] = col_wvec(j, W_joint, W_groups)[r0 + r];
    }
    __syncthreads();

    int c0 = t * 4;
    float acc[NCOL][4];
    #pragma unroll
    for (int j = 0; j < NCOL; j++)
        acc[j][0] = acc[j][1] = acc[j][2] = acc[j][3] = 0.f;

    #pragma unroll
    for (int r = 0; r < ROWS_PER_FOLD; r++) {
        float4 w = *(const float4*)(W_phi + (size_t)(r0 + r) * HDIM + c0);
        #pragma unroll
        for (int j = 0; j < NCOL; j++) {
            float v = sV[r][j];
            acc[j][0] += v * w.x; acc[j][1] += v * w.y;
            acc[j][2] += v * w.z; acc[j][3] += v * w.w;
        }
    }
    #pragma unroll
    for (int j = 0; j < NCOL; j++)
        *(float4*)&g_part[k][j][c0] = make_float4(acc[j][0], acc[j][1], acc[j][2], acc[j][3]);
}

// ---------------------------------------------------------------------------
// Fold stage 2: blocks 0..95 reduce 256 partials (split-k by 4); block 96 bias.
// ---------------------------------------------------------------------------
__global__ void __launch_bounds__(256) fold_reduce_kernel(const float* __restrict__ b_phi,
                                                          const float* __restrict__ W_groups,
                                                          const float* __restrict__ b_groups,
                                                          const float* __restrict__ W_joint,
                                                          const float* __restrict__ b_joint) {
    if (blockIdx.x == 96) {
        int w = threadIdx.x >> 5, lane = threadIdx.x & 31;
        if (w >= NCOL) return;
        const float* wv = col_wvec(w, W_joint, W_groups);
        float s = 0.f;
        #pragma unroll 4
        for (int h = lane; h < HDIM; h += 32) s += b_phi[h] * wv[h];
        #pragma unroll
        for (int o = 16; o > 0; o >>= 1) s += __shfl_down_sync(0xffffffffu, s, o);
        if (lane == 0) g_bias[w] = s + ((w < 2) ? b_joint[w] : b_groups[w - 2]);
        return;
    }
    __shared__ float red[256];
    int t = threadIdx.x;
    int idx = blockIdx.x * 64 + (t & 63);     // 96*64 = 6144 outputs
    int qk  = t >> 6;
    const float* p = (const float*)g_part;
    float s = 0.f;
    #pragma unroll 8
    for (int k = 0; k < FOLD_BLOCKS / 4; k++)
        s += p[(size_t)(qk * (FOLD_BLOCKS / 4) + k) * NCOL * HDIM + idx];
    red[t] = s;
    __syncthreads();
    if (t < 64)
        g_M[blockIdx.x * 64 + t] = (red[t] + red[t + 64]) + (red[t + 128] + red[t + 192]);
}

// ---------------------------------------------------------------------------
// Main: warp-cooperative, barrier-free; packed f32x2 FMAs; single u64 acc per
// (j,row); prefetch distance 2 via fully-unrolled ping-pong; 2 blocks/SM.
// ---------------------------------------------------------------------------
__global__ void __launch_bounds__(256, 2) main_kernel(const float* __restrict__ X,
                                                      const int* __restrict__ D,
                                                      const int* __restrict__ Dagn,
                                                      float* __restrict__ out) {
    __shared__ __align__(16) float sM[NCOL * HDIM];   // 24 KB, [j][h]
    __shared__ float sb[NCOL];
    int t = threadIdx.x;
    {
        const float4* src = (const float4*)g_M;
        float4* dst = (float4*)sM;
        #pragma unroll
        for (int i = 0; i < (NCOL * HDIM / 4) / 256; i++)
            dst[t + i * 256] = src[t + i * 256];
        if (t < NCOL) sb[t] = g_bias[t];
    }
    __syncthreads();

    int lane = t & 31, w = t >> 5;
    int sub = lane >> 3;          // row within 4-row group
    int q   = lane & 7;           // 128B-column slot
    int q4  = q * 4;

    int R0 = blockIdx.x * 128 + w * 16;           // warp's 16 rows
    const float* xb = X + (size_t)(R0 + sub) * HDIM + q4;

    u64 acc[NCOL][4];             // 24 u64 = 48 regs (was 96)
    #pragma unroll
    for (int j = 0; j < NCOL; j++)
        #pragma unroll
        for (int rr = 0; rr < 4; rr++)
            acc[j][rr] = 0ull;

    // ping-pong buffers, prefetch distance 2
    ulonglong2 b0[4], b1[4];
    #pragma unroll
    for (int rr = 0; rr < 4; rr++) {
        b0[rr] = __ldcs((const ulonglong2*)(xb + (size_t)(4 * rr) * HDIM + 0 * 32));
        b1[rr] = __ldcs((const ulonglong2*)(xb + (size_t)(4 * rr) * HDIM + 1 * 32));
    }

    #pragma unroll
    for (int ii = 0; ii < 16; ii++) {
        const int i = 2 * ii;
        // prefetch i+2 (before consuming b0), compute chunk i from b0
        ulonglong2 t0[4];
        if (i + 2 < 32) {
            #pragma unroll
            for (int rr = 0; rr < 4; rr++)
                t0[rr] = __ldcs((const ulonglong2*)(xb + (size_t)(4 * rr) * HDIM + (i + 2) * 32));
        }
        {
            const float* mb = sM + i * 32 + q4;
            #pragma unroll
            for (int j = 0; j < NCOL; j++) {
                ulonglong2 m = *(const ulonglong2*)(mb + j * HDIM);   // 128B line, bcast
                #pragma unroll
                for (int rr = 0; rr < 4; rr++) {
                    ffma2(acc[j][rr], b0[rr].x, m.x);
                    ffma2(acc[j][rr], b0[rr].y, m.y);
                }
            }
        }
        #pragma unroll
        for (int rr = 0; rr < 4; rr++) b0[rr] = t0[rr];

        // prefetch i+3 (before consuming b1), compute chunk i+1 from b1
        ulonglong2 t1[4];
        if (i + 3 < 32) {
            #pragma unroll
            for (int rr = 0; rr < 4; rr++)
                t1[rr] = __ldcs((const ulonglong2*)(xb + (size_t)(4 * rr) * HDIM + (i + 3) * 32));
        }
        {
            const float* mb = sM + (i + 1) * 32 + q4;
            #pragma unroll
            for (int j = 0; j < NCOL; j++) {
                ulonglong2 m = *(const ulonglong2*)(mb + j * HDIM);
                #pragma unroll
                for (int rr = 0; rr < 4; rr++) {
                    ffma2(acc[j][rr], b1[rr].x, m.x);
                    ffma2(acc[j][rr], b1[rr].y, m.y);
                }
            }
        }
        #pragma unroll
        for (int rr = 0; rr < 4; rr++) b1[rr] = t1[rr];
    }

    // collapse packed halves, then butterfly over q (lane bits 0..2)
    float a[NCOL][4];
    #pragma unroll
    for (int j = 0; j < NCOL; j++)
        #pragma unroll
        for (int rr = 0; rr < 4; rr++) {
            float s = unpack_sum(acc[j][rr]);
            #pragma unroll
            for (int o = 1; o < 8; o <<= 1) s += __shfl_xor_sync(0xffffffffu, s, o);
            a[j][rr] = s;
        }

    if (q == 0) {
        #pragma unroll
        for (int rr = 0; rr < 4; rr++) {
            int row = R0 + sub + 4 * rr;
            int d  = D[row];
            int da = Dagn[row];
            float j0  = a[0][rr] + sb[0], j1  = a[1][rr] + sb[1];
            float g00 = a[2][rr] + sb[2], g01 = a[3][rr] + sb[3];
            float g10 = a[4][rr] + sb[4], g11 = a[5][rr] + sb[5];
            *(float2*)(out + (size_t)row * 2) = make_float2(j0, j1);
            float2 gs = (d == 0)  ? make_float2(g00, g01) : make_float2(g10, g11);
            *(float2*)(out + (size_t)(BNUM + row) * 2) = gs;
            float2 ga = (da == 0) ? make_float2(g00, g01) : make_float2(g10, g11);
            *(float2*)(out + (size_t)(2 * BNUM + row) * 2) = ga;
        }
    }
}

// ---------------------------------------------------------------------------
extern "C" void kernel_launch(void* const* d_in, const int* in_sizes, int n_in,
                              void* d_out, int out_size) {
    const float* X        = (const float*)d_in[0];
    const float* W_phi    = (const float*)d_in[1];
    const float* b_phi    = (const float*)d_in[2];
    const float* W_groups = (const float*)d_in[3];
    const float* b_groups = (const float*)d_in[4];
    const float* W_joint  = (const float*)d_in[5];
    const float* b_joint  = (const float*)d_in[6];
    const int*   D        = (const int*)d_in[7];
    const int*   Dagn     = (const int*)d_in[8];
    float* out = (float*)d_out;

    fold_part_kernel<<<FOLD_BLOCKS, 256>>>(W_phi, W_groups, W_joint);
    fold_reduce_kernel<<<97, 256>>>(b_phi, W_groups, b_groups, W_joint, b_joint);
    main_kernel<<<BNUM / 128, 256>>>(X, D, Dagn, out);
}